// round 2
// baseline (speedup 1.0000x reference)
#include <cuda_runtime.h>
#include <cuda_bf16.h>
#include <math.h>

// ---------------- constants ----------------
#define L 256       // tokens
#define C 384       // channels
#define NH 12
#define HD 32
#define MLPD 1536
#define NB 12
#define INV_S 0.99999500003749968f   // 1/sqrt(1+1e-5)

// ---------------- scratch (device globals; no allocs allowed) ----------------
__device__ float g_t[L * C];            // token buffer (residual stream)
__device__ float g_y[L * C];            // LN1 + shift + window order
__device__ float g_qkv[L * 3 * C];      // qkv, window order
__device__ float g_att[L * C];          // attention out, window order
__device__ float g_z[L * C];            // LN2 out
__device__ float g_h1[L * MLPD];        // fc1+gelu out
__device__ float g_col[L * 768];        // im2col for patch embed
__device__ float g_d1[3 * 256 * 256];   // decoder stage-1
__device__ float g_skip[4 * 16 * 16];   // skip features

// ---------------- helpers ----------------
__device__ __forceinline__ unsigned f2tf(float x) {
    unsigned r; asm("cvt.rna.tf32.f32 %0, %1;" : "=r"(r) : "f"(x)); return r;
}

__device__ __forceinline__ void mma_tf32(float c[4], unsigned a0, unsigned a1,
                                         unsigned a2, unsigned a3,
                                         unsigned b0, unsigned b1)
{
    asm volatile(
        "mma.sync.aligned.m16n8k8.row.col.f32.tf32.tf32.f32 "
        "{%0,%1,%2,%3}, {%4,%5,%6,%7}, {%8,%9}, {%0,%1,%2,%3};"
        : "+f"(c[0]), "+f"(c[1]), "+f"(c[2]), "+f"(c[3])
        : "r"(a0), "r"(a1), "r"(a2), "r"(a3), "r"(b0), "r"(b1));
}

// epilogue kinds
#define EPI_PATCH 0
#define EPI_QKV   1
#define EPI_PROJ  2
#define EPI_GELU  3
#define EPI_RES   4

template<int EPI>
__device__ __forceinline__ void epi_apply(int m, int n, float v, int N,
                                          const float* __restrict__ bias,
                                          float* __restrict__ dst,
                                          const float* __restrict__ aux)
{
    if (EPI == EPI_QKV) {
        dst[(size_t)m * N + n] = v;
    } else if (EPI == EPI_PATCH) {
        int o = n * 256 + m;                     // buggy-flatten transpose
        dst[o] = v + bias[n] + aux[o];           // aux = pos_embed
    } else if (EPI == EPI_GELU) {
        float s = v + bias[n];
        dst[(size_t)m * MLPD + n] = 0.5f * s * (1.0f + erff(s * 0.70710678118654752f));
    } else if (EPI == EPI_RES) {
        dst[(size_t)m * C + n] += v + bias[n];
    } else { // EPI_PROJ: window row -> spatial (shifted) -> unshift, residual add
        int wi = m >> 6, pos = m & 63;
        int hs = ((wi >> 1) << 3) + (pos >> 3);
        int ws = ((wi & 1) << 3) + (pos & 7);
        int h = (hs + 4) & 15, w = (ws + 4) & 15;
        dst[(size_t)(h * 16 + w) * C + n] += v + bias[n];
    }
}

// ---------------- TF32 tensor-core GEMM: out = A(M,K) @ B(N,K)^T, fused epilogue ----
// CTA: 256 threads (8 warps: 4 in M, 2 in N), tile 64x64, BK=32, double-buffered.
// M, N, K all multiples of 64/64/32 for our shapes.
template<int EPI>
__global__ __launch_bounds__(256) void gemm_tf32(
    const float* __restrict__ A, const float* __restrict__ Bw,
    const float* __restrict__ bias, float* __restrict__ dst,
    const float* __restrict__ aux, int N, int K)
{
    __shared__ unsigned As[2][64][36];
    __shared__ unsigned Bs[2][64][36];
    const int bm = blockIdx.y * 64, bn = blockIdx.x * 64;
    const int tid = threadIdx.x;
    const int warp = tid >> 5, lane = tid & 31;
    const int wm = warp & 3, wn = warp >> 2;
    const int grp = lane >> 2, tig = lane & 3;
    const int lr = tid >> 2, lc = (tid & 3) * 8;

    float c[4][4];
#pragma unroll
    for (int i = 0; i < 4; i++)
#pragma unroll
        for (int j = 0; j < 4; j++) c[i][j] = 0.f;

    const float* Ap = A + (size_t)(bm + lr) * K + lc;
    const float* Bp = Bw + (size_t)(bn + lr) * K + lc;

    float4 ra0 = *(const float4*)(Ap);
    float4 ra1 = *(const float4*)(Ap + 4);
    float4 rb0 = *(const float4*)(Bp);
    float4 rb1 = *(const float4*)(Bp + 4);

    // stage 0 store
    {
        unsigned* as = &As[0][lr][lc];
        as[0] = f2tf(ra0.x); as[1] = f2tf(ra0.y); as[2] = f2tf(ra0.z); as[3] = f2tf(ra0.w);
        as[4] = f2tf(ra1.x); as[5] = f2tf(ra1.y); as[6] = f2tf(ra1.z); as[7] = f2tf(ra1.w);
        unsigned* bs = &Bs[0][lr][lc];
        bs[0] = f2tf(rb0.x); bs[1] = f2tf(rb0.y); bs[2] = f2tf(rb0.z); bs[3] = f2tf(rb0.w);
        bs[4] = f2tf(rb1.x); bs[5] = f2tf(rb1.y); bs[6] = f2tf(rb1.z); bs[7] = f2tf(rb1.w);
    }
    __syncthreads();

    const int nt = K >> 5;
    for (int it = 0; it < nt; it++) {
        int buf = it & 1;
        if (it + 1 < nt) {
            const float* ap = Ap + (it + 1) * 32;
            const float* bp = Bp + (it + 1) * 32;
            ra0 = *(const float4*)(ap);
            ra1 = *(const float4*)(ap + 4);
            rb0 = *(const float4*)(bp);
            rb1 = *(const float4*)(bp + 4);
        }
#pragma unroll
        for (int ks = 0; ks < 4; ks++) {
            int kk = ks * 8;
            unsigned a0 = As[buf][wm * 16 + grp][kk + tig];
            unsigned a1 = As[buf][wm * 16 + grp + 8][kk + tig];
            unsigned a2 = As[buf][wm * 16 + grp][kk + tig + 4];
            unsigned a3 = As[buf][wm * 16 + grp + 8][kk + tig + 4];
#pragma unroll
            for (int nb = 0; nb < 4; nb++) {
                unsigned b0 = Bs[buf][wn * 32 + nb * 8 + grp][kk + tig];
                unsigned b1 = Bs[buf][wn * 32 + nb * 8 + grp][kk + tig + 4];
                mma_tf32(c[nb], a0, a1, a2, a3, b0, b1);
            }
        }
        if (it + 1 < nt) {
            int nxt = 1 - buf;
            unsigned* as = &As[nxt][lr][lc];
            as[0] = f2tf(ra0.x); as[1] = f2tf(ra0.y); as[2] = f2tf(ra0.z); as[3] = f2tf(ra0.w);
            as[4] = f2tf(ra1.x); as[5] = f2tf(ra1.y); as[6] = f2tf(ra1.z); as[7] = f2tf(ra1.w);
            unsigned* bs = &Bs[nxt][lr][lc];
            bs[0] = f2tf(rb0.x); bs[1] = f2tf(rb0.y); bs[2] = f2tf(rb0.z); bs[3] = f2tf(rb0.w);
            bs[4] = f2tf(rb1.x); bs[5] = f2tf(rb1.y); bs[6] = f2tf(rb1.z); bs[7] = f2tf(rb1.w);
            __syncthreads();
        }
    }

    // epilogue
    int r0 = bm + wm * 16 + grp;
    int r1 = r0 + 8;
#pragma unroll
    for (int nb = 0; nb < 4; nb++) {
        int col = bn + wn * 32 + nb * 8 + tig * 2;
        epi_apply<EPI>(r0, col,     c[nb][0], N, bias, dst, aux);
        epi_apply<EPI>(r0, col + 1, c[nb][1], N, bias, dst, aux);
        epi_apply<EPI>(r1, col,     c[nb][2], N, bias, dst, aux);
        epi_apply<EPI>(r1, col + 1, c[nb][3], N, bias, dst, aux);
    }
}

// ---------------- LayerNorm (optionally fused shift + window partition) ----------------
template <bool SW>
__global__ void ln_kernel(const float* __restrict__ t, const float* __restrict__ w,
                          const float* __restrict__ bb, float* __restrict__ y)
{
    int hw = blockIdx.x;
    int tid = threadIdx.x;   // 128 threads, 3 elems each
    int srcRow, dstRow;
    if (SW) {
        int h = hw >> 4, wd = hw & 15;
        srcRow = (((h + 4) & 15) << 4) + ((wd + 4) & 15);
        int wi = ((h >> 3) << 1) + (wd >> 3);
        int pos = ((h & 7) << 3) + (wd & 7);
        dstRow = wi * 64 + pos;
    } else {
        srcRow = hw; dstRow = hw;
    }
    const float* src = t + srcRow * C;
    float x0 = src[tid], x1 = src[tid + 128], x2 = src[tid + 256];
    __shared__ float red[4];
    float s = x0 + x1 + x2;
#pragma unroll
    for (int o = 16; o; o >>= 1) s += __shfl_xor_sync(0xffffffffu, s, o);
    if ((tid & 31) == 0) red[tid >> 5] = s;
    __syncthreads();
    float mean = (red[0] + red[1] + red[2] + red[3]) * (1.0f / 384.0f);
    float d0 = x0 - mean, d1 = x1 - mean, d2 = x2 - mean;
    float s2 = d0 * d0 + d1 * d1 + d2 * d2;
#pragma unroll
    for (int o = 16; o; o >>= 1) s2 += __shfl_xor_sync(0xffffffffu, s2, o);
    __syncthreads();
    if ((tid & 31) == 0) red[tid >> 5] = s2;
    __syncthreads();
    float var = (red[0] + red[1] + red[2] + red[3]) * (1.0f / 384.0f);
    float rstd = rsqrtf(var + 1e-5f);
    float* dst = y + dstRow * C;
    dst[tid]       = d0 * rstd * w[tid]       + bb[tid];
    dst[tid + 128] = d1 * rstd * w[tid + 128] + bb[tid + 128];
    dst[tid + 256] = d2 * rstd * w[tid + 256] + bb[tid + 256];
}

// ---------------- windowed attention ----------------
__device__ __forceinline__ int region3(int h) { return h < 8 ? 0 : (h < 12 ? 1 : 2); }

__global__ void attn_kernel(const float* __restrict__ qkv, const float* __restrict__ rpb,
                            float* __restrict__ att)
{
    int wi = blockIdx.x / NH;
    int hd = blockIdx.x % NH;
    __shared__ float ks[64][32];
    __shared__ float vs[64][32];
    int tid = threadIdx.x;   // 64 threads, thread = query row
    const float* base = qkv + (size_t)wi * 64 * (3 * C) + hd * HD;
    float q[32];
#pragma unroll
    for (int d4 = 0; d4 < 8; d4++) {
        float4 kv = *(const float4*)(base + (size_t)tid * (3 * C) + C + d4 * 4);
        *(float4*)&ks[tid][d4 * 4] = kv;
        float4 vv = *(const float4*)(base + (size_t)tid * (3 * C) + 2 * C + d4 * 4);
        *(float4*)&vs[tid][d4 * 4] = vv;
        float4 qv = *(const float4*)(base + (size_t)tid * (3 * C) + d4 * 4);
        q[d4 * 4 + 0] = qv.x; q[d4 * 4 + 1] = qv.y; q[d4 * 4 + 2] = qv.z; q[d4 * 4 + 3] = qv.w;
    }
    __syncthreads();

    int i = tid;
    int yi = i >> 3, xi = i & 7;
    int ri = region3(((wi >> 1) << 3) + yi) * 3 + region3(((wi & 1) << 3) + xi);
    const float scale = 0.17677669529663687f;
    float s[64];
#pragma unroll 4
    for (int j = 0; j < 64; j++) {
        float acc = 0.f;
#pragma unroll
        for (int d = 0; d < 32; d++) acc += q[d] * ks[j][d];
        int yj = j >> 3, xj = j & 7;
        int rel = (yi - yj + 7) * 15 + (xi - xj + 7);
        float bias = rpb[rel * NH + hd];
        int rj = region3(((wi >> 1) << 3) + yj) * 3 + region3(((wi & 1) << 3) + xj);
        float mask = (ri == rj) ? 0.f : -100.f;
        s[j] = acc * scale + bias + mask;
    }
    float mx = -1e30f;
#pragma unroll
    for (int j = 0; j < 64; j++) mx = fmaxf(mx, s[j]);
    float sum = 0.f;
#pragma unroll
    for (int j = 0; j < 64; j++) { s[j] = expf(s[j] - mx); sum += s[j]; }
    float inv = 1.0f / sum;
    float* o = att + (size_t)(wi * 64 + i) * C + hd * HD;
#pragma unroll
    for (int d = 0; d < 32; d++) {
        float acc = 0.f;
#pragma unroll 8
        for (int j = 0; j < 64; j++) acc += s[j] * vs[j][d];
        o[d] = acc * inv;
    }
}

// ---------------- patch embed im2col ----------------
__global__ void im2col_kernel(const float* __restrict__ x, float* __restrict__ col)
{
    int i = blockIdx.x * 256 + threadIdx.x;   // < 256*768
    if (i >= 256 * 768) return;
    int patch = i / 768, r = i % 768;
    int c = r >> 8, pq = r & 255, p = pq >> 4, q = pq & 15;
    int h = patch >> 4, w = patch & 15;
    col[i] = x[c * 65536 + (h * 16 + p) * 256 + (w * 16 + q)];
}

// ---------------- decoder: skip 1x1 conv ----------------
__global__ void skip_kernel(const float* __restrict__ t, const float* __restrict__ sw,
                            const float* __restrict__ sb, float* __restrict__ skip)
{
    int i = blockIdx.x * 256 + threadIdx.x;   // < 1024
    if (i >= 1024) return;
    int o = i >> 8, hw = i & 255;
    float acc = sb[o];
    for (int c = 0; c < C; c++) acc += t[hw * C + c] * sw[o * C + c];
    skip[i] = acc;
}

// ---------------- decoder stage 1: deconv(C->3, k16 s16) + BN + ReLU ----------------
__global__ __launch_bounds__(768) void d1_kernel(
    const float* __restrict__ t, const float* __restrict__ w1, const float* __restrict__ b1,
    const float* __restrict__ bnw, const float* __restrict__ bnb, float* __restrict__ d1)
{
    __shared__ float ts[8][384];
    int tid = threadIdx.x;               // 768 = 3 * 256
    int p0 = blockIdx.x * 8;             // 32 blocks x 8 patches
#pragma unroll
    for (int v = 0; v < 4; v++) {
        int idx = v * 768 + tid;
        ts[idx / 384][idx % 384] = t[(p0 + idx / 384) * C + (idx % 384)];
    }
    __syncthreads();
    int o = tid >> 8;
    float acc[8];
#pragma unroll
    for (int g = 0; g < 8; g++) acc[g] = b1[o];
    for (int c = 0; c < C; c++) {
        float wv = w1[c * 768 + tid];
#pragma unroll
        for (int g = 0; g < 8; g++) acc[g] += ts[g][c] * wv;
    }
    float a = bnw[o] * INV_S, bbv = bnb[o];
    int k = (tid >> 4) & 15, l = tid & 15;
#pragma unroll
    for (int g = 0; g < 8; g++) {
        int patch = p0 + g;
        int h = patch >> 4, w = patch & 15;
        d1[o * 65536 + (h * 16 + k) * 256 + (w * 16 + l)] = fmaxf(0.f, acc[g] * a + bbv);
    }
}

// ---------------- decoder final (vectorized float4 stores) ----------------
__global__ void final_kernel(const float* __restrict__ d1, const float* __restrict__ w2,
                             const float* __restrict__ b2, const float* __restrict__ bnw,
                             const float* __restrict__ bnb, const float* __restrict__ skip,
                             float4* __restrict__ out)
{
    int idx4 = blockIdx.x * 256 + threadIdx.x;   // < 16,777,216
    int idx = idx4 << 2;
    int o = idx >> 24;
    int rem = idx & 0xFFFFFF;
    int Y = rem >> 12, X = rem & 4095;           // X, X+1, X+2, X+3 (same Y, same W)
    int H = Y >> 4, k = Y & 15, W = X >> 4;
    float d0 = d1[0 * 65536 + H * 256 + W];
    float d1v = d1[1 * 65536 + H * 256 + W];
    float d2 = d1[2 * 65536 + H * 256 + W];
    float bnwo = bnw[o] * INV_S, bnbo = bnb[o], b2o = b2[o];
    // vertical bilinear coords (shared across 4)
    int y0 = Y / 273;
    float fy = (float)(Y - y0 * 273) * (1.0f / 273.0f);
    int y1 = min(y0 + 1, 15);
    const float* sk = skip + o * 256;
    float r[4];
#pragma unroll
    for (int j = 0; j < 4; j++) {
        int Xj = X + j;
        int l = Xj & 15;
        int kl = k * 16 + l;
        float acc = b2o + d0 * w2[0 * 1024 + o * 256 + kl]
                        + d1v * w2[1 * 1024 + o * 256 + kl]
                        + d2 * w2[2 * 1024 + o * 256 + kl];
        acc = acc * bnwo + bnbo;
        int x0 = Xj / 273;
        float fx = (float)(Xj - x0 * 273) * (1.0f / 273.0f);
        int x1 = min(x0 + 1, 15);
        float v00 = sk[y0 * 16 + x0], v01 = sk[y0 * 16 + x1];
        float v10 = sk[y1 * 16 + x0], v11 = sk[y1 * 16 + x1];
        float vt = v00 + (v01 - v00) * fx;
        float vb = v10 + (v11 - v10) * fx;
        r[j] = acc + vt + (vb - vt) * fy;
    }
    out[idx4] = make_float4(r[0], r[1], r[2], r[3]);
}

// ---------------- host launch ----------------
extern "C" void kernel_launch(void* const* d_in, const int* in_sizes, int n_in,
                              void* d_out, int out_size)
{
    const float* x       = (const float*)d_in[0];
    const float* patch_w = (const float*)d_in[1];
    const float* patch_b = (const float*)d_in[2];
    const float* pos     = (const float*)d_in[3];
    const float* ln1_w   = (const float*)d_in[4];
    const float* ln1_b   = (const float*)d_in[5];
    const float* qkv_w   = (const float*)d_in[6];
    const float* proj_w  = (const float*)d_in[7];
    const float* proj_b  = (const float*)d_in[8];
    const float* rpb     = (const float*)d_in[9];
    const float* ln2_w   = (const float*)d_in[10];
    const float* ln2_b   = (const float*)d_in[11];
    const float* fc1_w   = (const float*)d_in[12];
    const float* fc1_b   = (const float*)d_in[13];
    const float* fc2_w   = (const float*)d_in[14];
    const float* fc2_b   = (const float*)d_in[15];
    const float* skip_w  = (const float*)d_in[16];
    const float* skip_b  = (const float*)d_in[17];
    const float* dt1_w   = (const float*)d_in[18];
    const float* dt1_b   = (const float*)d_in[19];
    const float* bn1_w   = (const float*)d_in[20];
    const float* bn1_b   = (const float*)d_in[21];
    const float* dt2_w   = (const float*)d_in[22];
    const float* dt2_b   = (const float*)d_in[23];
    const float* bn2_w   = (const float*)d_in[24];
    const float* bn2_b   = (const float*)d_in[25];
    float* out = (float*)d_out;

    float *t, *y, *qkv, *att, *z, *h1, *col, *d1, *skip;
    cudaGetSymbolAddress((void**)&t,    g_t);
    cudaGetSymbolAddress((void**)&y,    g_y);
    cudaGetSymbolAddress((void**)&qkv,  g_qkv);
    cudaGetSymbolAddress((void**)&att,  g_att);
    cudaGetSymbolAddress((void**)&z,    g_z);
    cudaGetSymbolAddress((void**)&h1,   g_h1);
    cudaGetSymbolAddress((void**)&col,  g_col);
    cudaGetSymbolAddress((void**)&d1,   g_d1);
    cudaGetSymbolAddress((void**)&skip, g_skip);

    // ---- patch embed: im2col + tf32 GEMM fused with bias+pos+transpose ----
    im2col_kernel<<<768, 256>>>(x, col);
    gemm_tf32<EPI_PATCH><<<dim3(6, 4), 256>>>(col, patch_w, patch_b, t, pos, 384, 768);

    // ---- 12 transformer blocks ----
    for (int b = 0; b < NB; b++) {
        ln_kernel<true><<<256, 128>>>(t, ln1_w + b * C, ln1_b + b * C, y);
        gemm_tf32<EPI_QKV><<<dim3(18, 4), 256>>>(y, qkv_w + (size_t)b * 3 * C * C,
                                                 nullptr, qkv, nullptr, 1152, 384);
        attn_kernel<<<48, 64>>>(qkv, rpb + (size_t)b * 225 * NH, att);
        gemm_tf32<EPI_PROJ><<<dim3(6, 4), 256>>>(att, proj_w + (size_t)b * C * C,
                                                 proj_b + b * C, t, nullptr, 384, 384);
        ln_kernel<false><<<256, 128>>>(t, ln2_w + b * C, ln2_b + b * C, z);
        gemm_tf32<EPI_GELU><<<dim3(24, 4), 256>>>(z, fc1_w + (size_t)b * MLPD * C,
                                                  fc1_b + b * MLPD, h1, nullptr, 1536, 384);
        gemm_tf32<EPI_RES><<<dim3(6, 4), 256>>>(h1, fc2_w + (size_t)b * C * MLPD,
                                                fc2_b + b * C, t, nullptr, 384, 1536);
    }

    // ---- decoder ----
    skip_kernel<<<4, 256>>>(t, skip_w, skip_b, skip);
    d1_kernel<<<32, 768>>>(t, dt1_w, dt1_b, bn1_w, bn1_b, d1);
    final_kernel<<<65536, 256>>>(d1, dt2_w, dt2_b, bn2_w, bn2_b, skip, (float4*)out);
}

// round 4
// speedup vs baseline: 1.6682x; 1.6682x over previous
#include <cuda_runtime.h>
#include <math.h>

// ---------------- constants ----------------
#define L 256
#define C 384
#define NH 12
#define MLPD 1536
#define NB 12
#define NCTA 148
#define INV_S 0.99999500003749968f

// ---------------- scratch ----------------
__device__ float g_t[L * C];
__device__ float g_y[L * C];
__device__ float g_att[L * C];
__device__ float g_z[L * C];
__device__ float g_h1[L * MLPD];        // fc1 pre-activation (raw matmul, no bias)
__device__ float g_qkvp[2 * L * 3 * C]; // qkv split-K partials
__device__ float g_part[6 * L * C];     // generic split-K partials
__device__ float g_col[L * 768];
__device__ float g_d1[3 * 256 * 256];
__device__ float g_skip[4 * 256];

// ---------------- global barrier ----------------
__device__ unsigned g_cnt;
__device__ volatile unsigned g_gen;

__global__ void reset_kernel() {
    g_cnt = 0;
    g_gen = 0;
    __threadfence();
}

__device__ __forceinline__ void gsync() {
    __syncthreads();
    if (threadIdx.x == 0) {
        __threadfence();
        unsigned gen = g_gen;
        if (atomicAdd(&g_cnt, 1u) == NCTA - 1) {
            g_cnt = 0;
            __threadfence();
            g_gen = gen + 1;
        } else {
            while (g_gen == gen) { __nanosleep(40); }
        }
        __threadfence();
    }
    __syncthreads();
}

// ---------------- helpers ----------------
__device__ __forceinline__ unsigned f2tf(float x) {
    unsigned r; asm("cvt.rna.tf32.f32 %0, %1;" : "=r"(r) : "f"(x)); return r;
}
__device__ __forceinline__ void mma_tf32(float c[4], unsigned a0, unsigned a1,
                                         unsigned a2, unsigned a3,
                                         unsigned b0, unsigned b1)
{
    asm volatile(
        "mma.sync.aligned.m16n8k8.row.col.f32.tf32.tf32.f32 "
        "{%0,%1,%2,%3}, {%4,%5,%6,%7}, {%8,%9}, {%0,%1,%2,%3};"
        : "+f"(c[0]), "+f"(c[1]), "+f"(c[2]), "+f"(c[3])
        : "r"(a0), "r"(a1), "r"(a2), "r"(a3), "r"(b0), "r"(b1));
}
__device__ __forceinline__ float gelu_f(float s) {
    return 0.5f * s * (1.0f + erff(s * 0.70710678118654752f));
}

template<int AG>
__device__ __forceinline__ void load_a8(const float* ap, const float* bb,
                                        float4& r0, float4& r1)
{
    r0 = *(const float4*)ap; r1 = *(const float4*)(ap + 4);
    if (AG) {
        float4 b0 = *(const float4*)bb, b1 = *(const float4*)(bb + 4);
        r0.x = gelu_f(r0.x + b0.x); r0.y = gelu_f(r0.y + b0.y);
        r0.z = gelu_f(r0.z + b0.z); r0.w = gelu_f(r0.w + b0.w);
        r1.x = gelu_f(r1.x + b1.x); r1.y = gelu_f(r1.y + b1.y);
        r1.z = gelu_f(r1.z + b1.z); r1.w = gelu_f(r1.w + b1.w);
    }
}

typedef unsigned SmTile[64][36];
__device__ __forceinline__ void st_tile(unsigned (*T)[36], int lr, int lc,
                                        float4 r0, float4 r1)
{
    unsigned* p = &T[lr][lc];
    p[0] = f2tf(r0.x); p[1] = f2tf(r0.y); p[2] = f2tf(r0.z); p[3] = f2tf(r0.w);
    p[4] = f2tf(r1.x); p[5] = f2tf(r1.y); p[6] = f2tf(r1.z); p[7] = f2tf(r1.w);
}

// TF32 GEMM tile phase: out_raw = A(bm:+64, k0:k0+32*nt) @ B(bn:+64, same)^T
template<int AG>
__device__ void gemm_core(const float* __restrict__ A, int lda,
                          const float* __restrict__ abias,
                          const float* __restrict__ Bw, int ldb,
                          float* __restrict__ outp, int N,
                          int bm, int bn, int k0, int nt, char* smbase)
{
    SmTile* As = (SmTile*)smbase;
    SmTile* Bs = (SmTile*)(smbase + 18432);
    const int tid = threadIdx.x;
    const int warp = tid >> 5, lane = tid & 31;
    const int wm = warp & 3, wn = warp >> 2;
    const int grp = lane >> 2, tig = lane & 3;
    const int lr = tid >> 2, lc = (tid & 3) * 8;

    float c[4][4];
#pragma unroll
    for (int i = 0; i < 4; i++)
#pragma unroll
        for (int j = 0; j < 4; j++) c[i][j] = 0.f;

    const float* Ap = A + (size_t)(bm + lr) * lda + k0 + lc;
    const float* Bp = Bw + (size_t)(bn + lr) * ldb + k0 + lc;
    const float* bp = AG ? (abias + k0 + lc) : (const float*)0;

    float4 ra0, ra1, rb0, rb1;
    load_a8<AG>(Ap, bp, ra0, ra1);
    rb0 = *(const float4*)Bp; rb1 = *(const float4*)(Bp + 4);
    st_tile(As[0], lr, lc, ra0, ra1);
    st_tile(Bs[0], lr, lc, rb0, rb1);
    __syncthreads();

    for (int it = 0; it < nt; it++) {
        int buf = it & 1;
        if (it + 1 < nt) {
            load_a8<AG>(Ap + (it + 1) * 32, AG ? bp + (it + 1) * 32 : bp, ra0, ra1);
            rb0 = *(const float4*)(Bp + (it + 1) * 32);
            rb1 = *(const float4*)(Bp + (it + 1) * 32 + 4);
        }
#pragma unroll
        for (int ks = 0; ks < 4; ks++) {
            int kk = ks * 8;
            unsigned a0 = As[buf][wm * 16 + grp][kk + tig];
            unsigned a1 = As[buf][wm * 16 + grp + 8][kk + tig];
            unsigned a2 = As[buf][wm * 16 + grp][kk + tig + 4];
            unsigned a3 = As[buf][wm * 16 + grp + 8][kk + tig + 4];
#pragma unroll
            for (int nb = 0; nb < 4; nb++) {
                unsigned b0 = Bs[buf][wn * 32 + nb * 8 + grp][kk + tig];
                unsigned b1 = Bs[buf][wn * 32 + nb * 8 + grp][kk + tig + 4];
                mma_tf32(c[nb], a0, a1, a2, a3, b0, b1);
            }
        }
        if (it + 1 < nt) {
            st_tile(As[1 - buf], lr, lc, ra0, ra1);
            st_tile(Bs[1 - buf], lr, lc, rb0, rb1);
            __syncthreads();
        }
    }

    int r0 = bm + wm * 16 + grp, r1 = r0 + 8;
#pragma unroll
    for (int nb = 0; nb < 4; nb++) {
        int col = bn + wn * 32 + nb * 8 + tig * 2;
        outp[(size_t)r0 * N + col]     = c[nb][0];
        outp[(size_t)r0 * N + col + 1] = c[nb][1];
        outp[(size_t)r1 * N + col]     = c[nb][2];
        outp[(size_t)r1 * N + col + 1] = c[nb][3];
    }
}

__device__ __forceinline__ int region3(int h) { return h < 8 ? 0 : (h < 12 ? 1 : 2); }

// ---------------- parameters ----------------
struct MegaParams {
    const float *x, *patch_w, *patch_b, *pos;
    const float *ln1_w, *ln1_b, *qkv_w, *proj_w, *proj_b, *rpb;
    const float *ln2_w, *ln2_b, *fc1_w, *fc1_b, *fc2_w, *fc2_b;
    const float *skip_w, *skip_b, *dt1_w, *dt1_b, *bn1_w, *bn1_b;
};

// ---------------- the persistent megakernel ----------------
__global__ __launch_bounds__(256) void mega(MegaParams P)
{
    __shared__ __align__(16) char sm[36864];
    __shared__ float red[4];
    const int bid = blockIdx.x;
    const int tid = threadIdx.x;

    // P0: im2col
    for (int i = bid * 256 + tid; i < 256 * 768; i += NCTA * 256) {
        int patch = i / 768, r = i % 768;
        int ch = r >> 8, pq = r & 255, pp = pq >> 4, q = pq & 15;
        int h = patch >> 4, w = patch & 15;
        g_col[i] = P.x[ch * 65536 + (h * 16 + pp) * 256 + (w * 16 + q)];
    }
    gsync();

    // P1: patch GEMM (M=256, N=384, K=768, S=6)
    if (bid < 144) {
        int s = bid % 6, tile = bid / 6;
        int mt = tile & 3, ntl = tile >> 2;
        gemm_core<0>(g_col, 768, 0, P.patch_w, 768,
                     g_part + (size_t)s * (L * C), C, mt * 64, ntl * 64, s * 128, 4, sm);
    }
    gsync();

    // P2: patch reduce + bias + pos + buggy transpose
    for (int i = bid * 256 + tid; i < L * C; i += NCTA * 256) {
        int m = i / C, n = i % C;
        float v = P.patch_b[n];
#pragma unroll
        for (int s = 0; s < 6; s++) v += g_part[(size_t)s * (L * C) + i];
        int o = n * 256 + m;
        g_t[o] = v + P.pos[o];
    }
    gsync();

    for (int b = 0; b < NB; b++) {
        // ---- LN1 (+fold prev fc2 partials+bias+residual), shift+window -> y ----
        {
            const float* fb = P.fc2_b + (b - 1) * C;
            const float* w  = P.ln1_w + b * C;
            const float* bv = P.ln1_b + b * C;
            for (int hw = bid; hw < 256; hw += NCTA) {
                int h = hw >> 4, wd = hw & 15;
                int srcRow = (((h + 4) & 15) << 4) + ((wd + 4) & 15);
                int wi = ((h >> 3) << 1) + (wd >> 3);
                int pos = ((h & 7) << 3) + (wd & 7);
                int dstRow = wi * 64 + pos;
                float x0 = 0.f, x1 = 0.f, x2 = 0.f;
                if (tid < 128) {
                    float* tr = g_t + srcRow * C;
                    x0 = tr[tid]; x1 = tr[tid + 128]; x2 = tr[tid + 256];
                    if (b > 0) {
                        float a0 = fb[tid], a1 = fb[tid + 128], a2 = fb[tid + 256];
#pragma unroll
                        for (int s = 0; s < 6; s++) {
                            const float* pq = g_part + (size_t)s * (L * C) + srcRow * C;
                            a0 += pq[tid]; a1 += pq[tid + 128]; a2 += pq[tid + 256];
                        }
                        x0 += a0; x1 += a1; x2 += a2;
                        tr[tid] = x0; tr[tid + 128] = x1; tr[tid + 256] = x2;
                    }
                }
                float s = x0 + x1 + x2;
#pragma unroll
                for (int o = 16; o; o >>= 1) s += __shfl_xor_sync(0xffffffffu, s, o);
                if (tid < 128 && (tid & 31) == 0) red[tid >> 5] = s;
                __syncthreads();
                float mean = (red[0] + red[1] + red[2] + red[3]) * (1.f / 384.f);
                float d0 = x0 - mean, d1 = x1 - mean, d2 = x2 - mean;
                float s2 = d0 * d0 + d1 * d1 + d2 * d2;
#pragma unroll
                for (int o = 16; o; o >>= 1) s2 += __shfl_xor_sync(0xffffffffu, s2, o);
                __syncthreads();
                if (tid < 128 && (tid & 31) == 0) red[tid >> 5] = s2;
                __syncthreads();
                float var = (red[0] + red[1] + red[2] + red[3]) * (1.f / 384.f);
                float rstd = rsqrtf(var + 1e-5f);
                if (tid < 128) {
                    float* dst = g_y + dstRow * C;
                    dst[tid]       = d0 * rstd * w[tid]       + bv[tid];
                    dst[tid + 128] = d1 * rstd * w[tid + 128] + bv[tid + 128];
                    dst[tid + 256] = d2 * rstd * w[tid + 256] + bv[tid + 256];
                }
                __syncthreads();
            }
        }
        gsync();

        // ---- qkv GEMM (M=256, N=1152, K=384, S=2) ----
        if (bid < 144) {
            int s = bid & 1, tile = bid >> 1;
            int mt = tile & 3, ntl = tile >> 2;     // ntl 0..17
            gemm_core<0>(g_y, 384, 0, P.qkv_w + (size_t)b * 3 * C * C, 384,
                         g_qkvp + (size_t)s * (L * 1152), 1152,
                         mt * 64, ntl * 64, s * 192, 6, sm);
        }
        gsync();

        // ---- attention (folds qkv partials) ----
        if (bid < 48) {
            int wi = bid / NH, hd = bid % NH;
            float (*ks)[32] = (float(*)[32])sm;
            float (*vs)[32] = (float(*)[32])(sm + 8192);
            float q[32];
            if (tid < 64) {
                const float* p0 = g_qkvp + (size_t)(wi * 64 + tid) * 1152 + hd * 32;
                const float* p1 = p0 + (size_t)L * 1152;
#pragma unroll
                for (int d4 = 0; d4 < 8; d4++) {
                    float4 qa = *(const float4*)(p0 + d4 * 4);
                    float4 qb = *(const float4*)(p1 + d4 * 4);
                    q[d4 * 4 + 0] = qa.x + qb.x; q[d4 * 4 + 1] = qa.y + qb.y;
                    q[d4 * 4 + 2] = qa.z + qb.z; q[d4 * 4 + 3] = qa.w + qb.w;
                    float4 ka = *(const float4*)(p0 + 384 + d4 * 4);
                    float4 kb = *(const float4*)(p1 + 384 + d4 * 4);
                    ks[tid][d4 * 4 + 0] = ka.x + kb.x; ks[tid][d4 * 4 + 1] = ka.y + kb.y;
                    ks[tid][d4 * 4 + 2] = ka.z + kb.z; ks[tid][d4 * 4 + 3] = ka.w + kb.w;
                    float4 va = *(const float4*)(p0 + 768 + d4 * 4);
                    float4 vb = *(const float4*)(p1 + 768 + d4 * 4);
                    vs[tid][d4 * 4 + 0] = va.x + vb.x; vs[tid][d4 * 4 + 1] = va.y + vb.y;
                    vs[tid][d4 * 4 + 2] = va.z + vb.z; vs[tid][d4 * 4 + 3] = va.w + vb.w;
                }
            }
            __syncthreads();
            if (tid < 64) {
                const float* rpb = P.rpb + (size_t)b * 225 * NH;
                int i = tid;
                int yi = i >> 3, xi = i & 7;
                int ri = region3(((wi >> 1) << 3) + yi) * 3 + region3(((wi & 1) << 3) + xi);
                const float scale = 0.17677669529663687f;
                float s[64];
#pragma unroll 4
                for (int j = 0; j < 64; j++) {
                    float acc = 0.f;
#pragma unroll
                    for (int d = 0; d < 32; d++) acc += q[d] * ks[j][d];
                    int yj = j >> 3, xj = j & 7;
                    int rel = (yi - yj + 7) * 15 + (xi - xj + 7);
                    float bias = rpb[rel * NH + hd];
                    int rj = region3(((wi >> 1) << 3) + yj) * 3 + region3(((wi & 1) << 3) + xj);
                    s[j] = acc * scale + bias + ((ri == rj) ? 0.f : -100.f);
                }
                float mx = -1e30f;
#pragma unroll
                for (int j = 0; j < 64; j++) mx = fmaxf(mx, s[j]);
                float sum = 0.f;
#pragma unroll
                for (int j = 0; j < 64; j++) { s[j] = expf(s[j] - mx); sum += s[j]; }
                float inv = 1.0f / sum;
                float* o = g_att + (size_t)(wi * 64 + i) * C + hd * 32;
#pragma unroll
                for (int d = 0; d < 32; d++) {
                    float acc = 0.f;
#pragma unroll 8
                    for (int j = 0; j < 64; j++) acc += s[j] * vs[j][d];
                    o[d] = acc * inv;
                }
            }
        }
        gsync();

        // ---- proj GEMM (M=256, N=384, K=384, S=4) ----
        if (bid < 96) {
            int s = bid & 3, tile = bid >> 2;
            int mt = tile & 3, ntl = tile >> 2;     // ntl 0..5
            gemm_core<0>(g_att, 384, 0, P.proj_w + (size_t)b * C * C, 384,
                         g_part + (size_t)s * (L * C), C, mt * 64, ntl * 64, s * 96, 3, sm);
        }
        gsync();

        // ---- LN2 (+fold proj partials w/ unshift + bias + residual) -> z ----
        {
            const float* pb = P.proj_b + b * C;
            const float* w  = P.ln2_w + b * C;
            const float* bv = P.ln2_b + b * C;
            for (int r = bid; r < 256; r += NCTA) {
                int h = r >> 4, wd = r & 15;
                int hs = (h + 12) & 15, ws_ = (wd + 12) & 15;
                int wi = ((hs >> 3) << 1) + (ws_ >> 3);
                int pos = ((hs & 7) << 3) + (ws_ & 7);
                int mw = wi * 64 + pos;
                float x0 = 0.f, x1 = 0.f, x2 = 0.f;
                if (tid < 128) {
                    float* tr = g_t + r * C;
                    float a0 = pb[tid], a1 = pb[tid + 128], a2 = pb[tid + 256];
#pragma unroll
                    for (int s = 0; s < 4; s++) {
                        const float* pq = g_part + (size_t)s * (L * C) + mw * C;
                        a0 += pq[tid]; a1 += pq[tid + 128]; a2 += pq[tid + 256];
                    }
                    x0 = tr[tid] + a0; x1 = tr[tid + 128] + a1; x2 = tr[tid + 256] + a2;
                    tr[tid] = x0; tr[tid + 128] = x1; tr[tid + 256] = x2;
                }
                float s = x0 + x1 + x2;
#pragma unroll
                for (int o = 16; o; o >>= 1) s += __shfl_xor_sync(0xffffffffu, s, o);
                if (tid < 128 && (tid & 31) == 0) red[tid >> 5] = s;
                __syncthreads();
                float mean = (red[0] + red[1] + red[2] + red[3]) * (1.f / 384.f);
                float d0 = x0 - mean, d1 = x1 - mean, d2 = x2 - mean;
                float s2 = d0 * d0 + d1 * d1 + d2 * d2;
#pragma unroll
                for (int o = 16; o; o >>= 1) s2 += __shfl_xor_sync(0xffffffffu, s2, o);
                __syncthreads();
                if (tid < 128 && (tid & 31) == 0) red[tid >> 5] = s2;
                __syncthreads();
                float var = (red[0] + red[1] + red[2] + red[3]) * (1.f / 384.f);
                float rstd = rsqrtf(var + 1e-5f);
                if (tid < 128) {
                    float* dst = g_z + r * C;
                    dst[tid]       = d0 * rstd * w[tid]       + bv[tid];
                    dst[tid + 128] = d1 * rstd * w[tid + 128] + bv[tid + 128];
                    dst[tid + 256] = d2 * rstd * w[tid + 256] + bv[tid + 256];
                }
                __syncthreads();
            }
        }
        gsync();

        // ---- fc1 GEMM (M=256, N=1536, K=384, S=1) -> raw preact ----
        if (bid < 96) {
            int mt = bid & 3, ntl = bid >> 2;       // ntl 0..23
            gemm_core<0>(g_z, 384, 0, P.fc1_w + (size_t)b * MLPD * C, 384,
                         g_h1, MLPD, mt * 64, ntl * 64, 0, 12, sm);
        }
        gsync();

        // ---- fc2 GEMM (M=256, N=384, K=1536, S=6), A = gelu(h1+b1) on the fly ----
        if (bid < 144) {
            int s = bid % 6, tile = bid / 6;
            int mt = tile & 3, ntl = tile >> 2;     // ntl 0..5
            gemm_core<1>(g_h1, MLPD, P.fc1_b + (size_t)b * MLPD,
                         P.fc2_w + (size_t)b * C * MLPD, MLPD,
                         g_part + (size_t)s * (L * C), C, mt * 64, ntl * 64, s * 256, 8, sm);
        }
        gsync();
    }

    // ---- fold last fc2 into t ----
    {
        const float* fb = P.fc2_b + 11 * C;
        for (int i = bid * 256 + tid; i < L * C; i += NCTA * 256) {
            int n = i % C;
            float v = fb[n];
#pragma unroll
            for (int s = 0; s < 6; s++) v += g_part[(size_t)s * (L * C) + i];
            g_t[i] += v;
        }
    }
    gsync();

    // ---- decoder: skip 1x1 conv + d1 deconv+BN+ReLU ----
    if (bid < 96) {
        int o = bid % 3, pg = bid / 3;
        float (*ts)[384] = (float(*)[384])sm;
        for (int i = tid; i < 8 * 384; i += 256)
            ts[i / 384][i % 384] = g_t[(pg * 8 + i / 384) * C + (i % 384)];
        __syncthreads();
        float acc[8];
#pragma unroll
        for (int g = 0; g < 8; g++) acc[g] = P.dt1_b[o];
        for (int cc = 0; cc < C; cc++) {
            float wv = P.dt1_w[cc * 768 + o * 256 + tid];
#pragma unroll
            for (int g = 0; g < 8; g++) acc[g] += ts[g][cc] * wv;
        }
        float a = P.bn1_w[o] * INV_S, bbv = P.bn1_b[o];
        int k = tid >> 4, l = tid & 15;
#pragma unroll
        for (int g = 0; g < 8; g++) {
            int patch = pg * 8 + g;
            int h = patch >> 4, w = patch & 15;
            g_d1[o * 65536 + (h * 16 + k) * 256 + (w * 16 + l)] =
                fmaxf(0.f, acc[g] * a + bbv);
        }
    } else if (bid < 100) {
        int o = bid - 96;
        float acc = P.skip_b[o];
        for (int cc = 0; cc < C; cc++) acc += g_t[tid * C + cc] * P.skip_w[o * C + cc];
        g_skip[o * 256 + tid] = acc;
    }
}

// ---------------- decoder final (separate, fully parallel) ----------------
__global__ void final_kernel(const float* __restrict__ w2,
                             const float* __restrict__ b2, const float* __restrict__ bnw,
                             const float* __restrict__ bnb, float4* __restrict__ out)
{
    int idx4 = blockIdx.x * 256 + threadIdx.x;
    int idx = idx4 << 2;
    int o = idx >> 24;
    int rem = idx & 0xFFFFFF;
    int Y = rem >> 12, X = rem & 4095;
    int H = Y >> 4, k = Y & 15, W = X >> 4;
    float d0 = g_d1[0 * 65536 + H * 256 + W];
    float d1v = g_d1[1 * 65536 + H * 256 + W];
    float d2 = g_d1[2 * 65536 + H * 256 + W];
    float bnwo = bnw[o] * INV_S, bnbo = bnb[o], b2o = b2[o];
    int y0 = Y / 273;
    float fy = (float)(Y - y0 * 273) * (1.0f / 273.0f);
    int y1 = min(y0 + 1, 15);
    const float* sk = g_skip + o * 256;
    float r[4];
#pragma unroll
    for (int j = 0; j < 4; j++) {
        int Xj = X + j;
        int l = Xj & 15;
        int kl = k * 16 + l;
        float acc = b2o + d0 * w2[0 * 1024 + o * 256 + kl]
                        + d1v * w2[1 * 1024 + o * 256 + kl]
                        + d2 * w2[2 * 1024 + o * 256 + kl];
        acc = acc * bnwo + bnbo;
        int x0 = Xj / 273;
        float fx = (float)(Xj - x0 * 273) * (1.0f / 273.0f);
        int x1 = min(x0 + 1, 15);
        float v00 = sk[y0 * 16 + x0], v01 = sk[y0 * 16 + x1];
        float v10 = sk[y1 * 16 + x0], v11 = sk[y1 * 16 + x1];
        float vt = v00 + (v01 - v00) * fx;
        float vb = v10 + (v11 - v10) * fx;
        r[j] = acc + vt + (vb - vt) * fy;
    }
    out[idx4] = make_float4(r[0], r[1], r[2], r[3]);
}

// ---------------- host launch ----------------
extern "C" void kernel_launch(void* const* d_in, const int* in_sizes, int n_in,
                              void* d_out, int out_size)
{
    MegaParams P;
    P.x       = (const float*)d_in[0];
    P.patch_w = (const float*)d_in[1];
    P.patch_b = (const float*)d_in[2];
    P.pos     = (const float*)d_in[3];
    P.ln1_w   = (const float*)d_in[4];
    P.ln1_b   = (const float*)d_in[5];
    P.qkv_w   = (const float*)d_in[6];
    P.proj_w  = (const float*)d_in[7];
    P.proj_b  = (const float*)d_in[8];
    P.rpb     = (const float*)d_in[9];
    P.ln2_w   = (const float*)d_in[10];
    P.ln2_b   = (const float*)d_in[11];
    P.fc1_w   = (const float*)d_in[12];
    P.fc1_b   = (const float*)d_in[13];
    P.fc2_w   = (const float*)d_in[14];
    P.fc2_b   = (const float*)d_in[15];
    P.skip_w  = (const float*)d_in[16];
    P.skip_b  = (const float*)d_in[17];
    P.dt1_w   = (const float*)d_in[18];
    P.dt1_b   = (const float*)d_in[19];
    P.bn1_w   = (const float*)d_in[20];
    P.bn1_b   = (const float*)d_in[21];
    const float* dt2_w = (const float*)d_in[22];
    const float* dt2_b = (const float*)d_in[23];
    const float* bn2_w = (const float*)d_in[24];
    const float* bn2_b = (const float*)d_in[25];

    reset_kernel<<<1, 1>>>();
    mega<<<NCTA, 256>>>(P);
    final_kernel<<<65536, 256>>>(dt2_w, dt2_b, bn2_w, bn2_b, (float4*)d_out);
}

// round 6
// speedup vs baseline: 2.3485x; 1.4078x over previous
#include <cuda_runtime.h>
#include <math.h>

// ---------------- constants ----------------
#define L 256
#define C 384
#define NH 12
#define MLPD 1536
#define NB 12
#define NCTA 148
#define INV_S 0.99999500003749968f
#define GEMM_SMEM (4 * 64 * 36 * 4)           // one operand, 4 stages
#define MEGA_SMEM (2 * GEMM_SMEM)             // 73728 bytes

// ---------------- scratch ----------------
__device__ __align__(16) float g_t[L * C];
__device__ __align__(16) float g_y[L * C];
__device__ __align__(16) float g_att[L * C];
__device__ __align__(16) float g_z[L * C];
__device__ __align__(16) float g_h1[L * MLPD];        // gelu(fc1) output
__device__ __align__(16) float g_qkvp[2 * L * 3 * C]; // qkv split-K partials
__device__ __align__(16) float g_part[6 * L * C];     // generic split-K partials
__device__ __align__(16) float g_col[L * 768];
__device__ __align__(16) float g_d1[3 * 256 * 256];
__device__ __align__(16) float g_skip[4 * 256];

// ---------------- global barrier ----------------
__device__ unsigned g_cnt;
__device__ volatile unsigned g_gen;

__global__ void reset_kernel() {
    g_cnt = 0;
    g_gen = 0;
    __threadfence();
}

__device__ __forceinline__ void gsync() {
    __syncthreads();
    if (threadIdx.x == 0) {
        __threadfence();
        unsigned gen = g_gen;
        if (atomicAdd(&g_cnt, 1u) == NCTA - 1) {
            g_cnt = 0;
            __threadfence();
            g_gen = gen + 1;
        } else {
            while (g_gen == gen) { }
        }
        __threadfence();
    }
    __syncthreads();
}

// ---------------- helpers ----------------
__device__ __forceinline__ void mma_tf32(float c[4], unsigned a0, unsigned a1,
                                         unsigned a2, unsigned a3,
                                         unsigned b0, unsigned b1)
{
    asm volatile(
        "mma.sync.aligned.m16n8k8.row.col.f32.tf32.tf32.f32 "
        "{%0,%1,%2,%3}, {%4,%5,%6,%7}, {%8,%9}, {%0,%1,%2,%3};"
        : "+f"(c[0]), "+f"(c[1]), "+f"(c[2]), "+f"(c[3])
        : "r"(a0), "r"(a1), "r"(a2), "r"(a3), "r"(b0), "r"(b1));
}
__device__ __forceinline__ float gelu_f(float s) {
    return 0.5f * s * (1.0f + erff(s * 0.70710678118654752f));
}
__device__ __forceinline__ void cp16(void* s, const void* g) {
    unsigned sa = (unsigned)__cvta_generic_to_shared(s);
    asm volatile("cp.async.cg.shared.global [%0], [%1], 16;" :: "r"(sa), "l"(g) : "memory");
}
#define CP_COMMIT() asm volatile("cp.async.commit_group;" ::: "memory")
#define CP_WAIT2()  asm volatile("cp.async.wait_group 2;" ::: "memory")

// round-to-nearest tf32: add half-ULP of 10-bit mantissa; HW ignores low 13 bits
__device__ __forceinline__ unsigned rnd_tf(float x) {
    return __float_as_uint(x) + 0x1000u;
}

// ---------------- TF32 GEMM, cp.async 4-stage pipeline ----------------
// out = A(bm:+64, k0:k0+32*nt) @ B(bn:+64, same)^T
// EPI: 0 = plain store, 1 = gelu(v + bias[n]) store
template<int EPI>
__device__ void gemm_core(const float* __restrict__ A, int lda,
                          const float* __restrict__ Bw, int ldb,
                          const float* __restrict__ bias,
                          float* __restrict__ outp, int N,
                          int bm, int bn, int k0, int nt, char* smbase)
{
    float (*As)[64][36] = (float(*)[64][36])smbase;
    float (*Bs)[64][36] = (float(*)[64][36])(smbase + GEMM_SMEM);
    const int tid = threadIdx.x;
    const int warp = tid >> 5, lane = tid & 31;
    const int wm = warp & 3, wn = warp >> 2;
    const int grp = lane >> 2, tig = lane & 3;
    const int lr = tid >> 2, lc = (tid & 3) * 8;

    float c[4][4];
#pragma unroll
    for (int i = 0; i < 4; i++)
#pragma unroll
        for (int j = 0; j < 4; j++) c[i][j] = 0.f;

    const float* Ap = A + (size_t)(bm + lr) * lda + k0 + lc;
    const float* Bp = Bw + (size_t)(bn + lr) * ldb + k0 + lc;

#pragma unroll
    for (int s = 0; s < 3; s++) {
        if (s < nt) {
            cp16(&As[s][lr][lc],     Ap + s * 32);
            cp16(&As[s][lr][lc + 4], Ap + s * 32 + 4);
            cp16(&Bs[s][lr][lc],     Bp + s * 32);
            cp16(&Bs[s][lr][lc + 4], Bp + s * 32 + 4);
        }
        CP_COMMIT();
    }

    for (int it = 0; it < nt; it++) {
        CP_WAIT2();
        __syncthreads();
        int buf = it & 3;
#pragma unroll
        for (int ks = 0; ks < 4; ks++) {
            int kk = ks * 8;
            unsigned a0 = rnd_tf(As[buf][wm * 16 + grp][kk + tig]);
            unsigned a1 = rnd_tf(As[buf][wm * 16 + grp + 8][kk + tig]);
            unsigned a2 = rnd_tf(As[buf][wm * 16 + grp][kk + tig + 4]);
            unsigned a3 = rnd_tf(As[buf][wm * 16 + grp + 8][kk + tig + 4]);
#pragma unroll
            for (int nb = 0; nb < 4; nb++) {
                unsigned b0 = rnd_tf(Bs[buf][wn * 32 + nb * 8 + grp][kk + tig]);
                unsigned b1 = rnd_tf(Bs[buf][wn * 32 + nb * 8 + grp][kk + tig + 4]);
                mma_tf32(c[nb], a0, a1, a2, a3, b0, b1);
            }
        }
        if (it + 3 < nt) {
            int nbuf = (it + 3) & 3;
            cp16(&As[nbuf][lr][lc],     Ap + (it + 3) * 32);
            cp16(&As[nbuf][lr][lc + 4], Ap + (it + 3) * 32 + 4);
            cp16(&Bs[nbuf][lr][lc],     Bp + (it + 3) * 32);
            cp16(&Bs[nbuf][lr][lc + 4], Bp + (it + 3) * 32 + 4);
        }
        CP_COMMIT();
    }

    int r0 = bm + wm * 16 + grp, r1 = r0 + 8;
#pragma unroll
    for (int nb = 0; nb < 4; nb++) {
        int col = bn + wn * 32 + nb * 8 + tig * 2;
        if (EPI == 0) {
            outp[(size_t)r0 * N + col]     = c[nb][0];
            outp[(size_t)r0 * N + col + 1] = c[nb][1];
            outp[(size_t)r1 * N + col]     = c[nb][2];
            outp[(size_t)r1 * N + col + 1] = c[nb][3];
        } else {
            float b0v = bias[col], b1v = bias[col + 1];
            outp[(size_t)r0 * N + col]     = gelu_f(c[nb][0] + b0v);
            outp[(size_t)r0 * N + col + 1] = gelu_f(c[nb][1] + b1v);
            outp[(size_t)r1 * N + col]     = gelu_f(c[nb][2] + b0v);
            outp[(size_t)r1 * N + col + 1] = gelu_f(c[nb][3] + b1v);
        }
    }
}

__device__ __forceinline__ int region3(int h) { return h < 8 ? 0 : (h < 12 ? 1 : 2); }

// ---------------- parameters ----------------
struct MegaParams {
    const float *x, *patch_w, *patch_b, *pos;
    const float *ln1_w, *ln1_b, *qkv_w, *proj_w, *proj_b, *rpb;
    const float *ln2_w, *ln2_b, *fc1_w, *fc1_b, *fc2_w, *fc2_b;
    const float *skip_w, *skip_b, *dt1_w, *dt1_b, *bn1_w, *bn1_b;
};

// ---------------- the persistent megakernel ----------------
__global__ __launch_bounds__(256) void mega(MegaParams P)
{
    extern __shared__ __align__(16) char sm[];
    __shared__ float red[4];
    const int bid = blockIdx.x;
    const int tid = threadIdx.x;

    // P0: im2col
    for (int i = bid * 256 + tid; i < 256 * 768; i += NCTA * 256) {
        int patch = i / 768, r = i % 768;
        int ch = r >> 8, pq = r & 255, pp = pq >> 4, q = pq & 15;
        int h = patch >> 4, w = patch & 15;
        g_col[i] = P.x[ch * 65536 + (h * 16 + pp) * 256 + (w * 16 + q)];
    }
    gsync();

    // P1: patch GEMM (M=256, N=384, K=768, S=6)
    if (bid < 144) {
        int s = bid % 6, tile = bid / 6;
        int mt = tile & 3, ntl = tile >> 2;
        gemm_core<0>(g_col, 768, P.patch_w, 768, 0,
                     g_part + (size_t)s * (L * C), C, mt * 64, ntl * 64, s * 128, 4, sm);
    }
    gsync();

    // P2: patch reduce + bias + pos + buggy transpose
    for (int i = bid * 256 + tid; i < L * C; i += NCTA * 256) {
        int m = i / C, n = i % C;
        float v = P.patch_b[n];
#pragma unroll
        for (int s = 0; s < 6; s++) v += g_part[(size_t)s * (L * C) + i];
        int o = n * 256 + m;
        g_t[o] = v + P.pos[o];
    }
    gsync();

    for (int blk = 0; blk < NB; blk++) {
        // ---- LN1 (+fold prev fc2 partials+bias+residual), shift+window -> y ----
        {
            const float* fb = P.fc2_b + (blk - 1) * C;
            const float* w  = P.ln1_w + blk * C;
            const float* bv = P.ln1_b + blk * C;
            for (int hw = bid; hw < 256; hw += NCTA) {
                int h = hw >> 4, wd = hw & 15;
                int srcRow = (((h + 4) & 15) << 4) + ((wd + 4) & 15);
                int wi = ((h >> 3) << 1) + (wd >> 3);
                int pos = ((h & 7) << 3) + (wd & 7);
                int dstRow = wi * 64 + pos;
                float x0 = 0.f, x1 = 0.f, x2 = 0.f;
                if (tid < 128) {
                    float* tr = g_t + srcRow * C;
                    x0 = tr[tid]; x1 = tr[tid + 128]; x2 = tr[tid + 256];
                    if (blk > 0) {
                        float a0 = fb[tid], a1 = fb[tid + 128], a2 = fb[tid + 256];
#pragma unroll
                        for (int s = 0; s < 6; s++) {
                            const float* pq = g_part + (size_t)s * (L * C) + srcRow * C;
                            a0 += pq[tid]; a1 += pq[tid + 128]; a2 += pq[tid + 256];
                        }
                        x0 += a0; x1 += a1; x2 += a2;
                        tr[tid] = x0; tr[tid + 128] = x1; tr[tid + 256] = x2;
                    }
                }
                float s = x0 + x1 + x2;
#pragma unroll
                for (int o = 16; o; o >>= 1) s += __shfl_xor_sync(0xffffffffu, s, o);
                if (tid < 128 && (tid & 31) == 0) red[tid >> 5] = s;
                __syncthreads();
                float mean = (red[0] + red[1] + red[2] + red[3]) * (1.f / 384.f);
                float d0 = x0 - mean, d1 = x1 - mean, d2 = x2 - mean;
                float s2 = d0 * d0 + d1 * d1 + d2 * d2;
#pragma unroll
                for (int o = 16; o; o >>= 1) s2 += __shfl_xor_sync(0xffffffffu, s2, o);
                __syncthreads();
                if (tid < 128 && (tid & 31) == 0) red[tid >> 5] = s2;
                __syncthreads();
                float var = (red[0] + red[1] + red[2] + red[3]) * (1.f / 384.f);
                float rstd = rsqrtf(var + 1e-5f);
                if (tid < 128) {
                    float* dst = g_y + dstRow * C;
                    dst[tid]       = d0 * rstd * w[tid]       + bv[tid];
                    dst[tid + 128] = d1 * rstd * w[tid + 128] + bv[tid + 128];
                    dst[tid + 256] = d2 * rstd * w[tid + 256] + bv[tid + 256];
                }
                __syncthreads();
            }
        }
        gsync();

        // ---- qkv GEMM (M=256, N=1152, K=384, S=2) ----
        if (bid < 144) {
            int s = bid & 1, tile = bid >> 1;
            int mt = tile & 3, ntl = tile >> 2;
            gemm_core<0>(g_y, 384, P.qkv_w + (size_t)blk * 3 * C * C, 384, 0,
                         g_qkvp + (size_t)s * (L * 1152), 1152,
                         mt * 64, ntl * 64, s * 192, 6, sm);
        }
        gsync();

        // ---- attention (folds qkv partials), 256 threads: 4 lanes per row ----
        if (bid < 48) {
            int wi = bid / NH, hd = bid % NH;
            float (*qs)[32] = (float(*)[32])sm;
            float (*ks)[32] = (float(*)[32])(sm + 8192);
            float (*vs)[32] = (float(*)[32])(sm + 16384);
            float (*ps)[68] = (float(*)[68])(sm + 24576);
            int row = tid >> 2, l4 = tid & 3;
            const float* p0 = g_qkvp + (size_t)(wi * 64 + row) * 1152 + hd * 32;
            const float* p1 = p0 + (size_t)L * 1152;
            int c0 = l4 * 8;
#pragma unroll
            for (int u = 0; u < 8; u += 4) {
                int cc = c0 + u;
                float4 a = *(const float4*)(p0 + cc);
                float4 bq = *(const float4*)(p1 + cc);
                qs[row][cc] = a.x + bq.x; qs[row][cc + 1] = a.y + bq.y;
                qs[row][cc + 2] = a.z + bq.z; qs[row][cc + 3] = a.w + bq.w;
                a = *(const float4*)(p0 + 384 + cc);
                bq = *(const float4*)(p1 + 384 + cc);
                ks[row][cc] = a.x + bq.x; ks[row][cc + 1] = a.y + bq.y;
                ks[row][cc + 2] = a.z + bq.z; ks[row][cc + 3] = a.w + bq.w;
                a = *(const float4*)(p0 + 768 + cc);
                bq = *(const float4*)(p1 + 768 + cc);
                vs[row][cc] = a.x + bq.x; vs[row][cc + 1] = a.y + bq.y;
                vs[row][cc + 2] = a.z + bq.z; vs[row][cc + 3] = a.w + bq.w;
            }
            __syncthreads();
            float qreg[32];
#pragma unroll
            for (int d = 0; d < 32; d++) qreg[d] = qs[row][d];
            int yi = row >> 3, xi = row & 7;
            int ri = region3(((wi >> 1) << 3) + yi) * 3 + region3(((wi & 1) << 3) + xi);
            const float* rpb = P.rpb + (size_t)blk * 225 * NH;
            const float scale = 0.17677669529663687f;
            float sl[16];
            int j0 = l4 * 16;
            float mx = -1e30f;
#pragma unroll
            for (int jj = 0; jj < 16; jj++) {
                int j = j0 + jj;
                float acc = 0.f;
#pragma unroll
                for (int d = 0; d < 32; d++) acc += qreg[d] * ks[j][d];
                int yj = j >> 3, xj = j & 7;
                float bias = rpb[((yi - yj + 7) * 15 + (xi - xj + 7)) * NH + hd];
                int rj = region3(((wi >> 1) << 3) + yj) * 3 + region3(((wi & 1) << 3) + xj);
                sl[jj] = acc * scale + bias + ((ri == rj) ? 0.f : -100.f);
                mx = fmaxf(mx, sl[jj]);
            }
            mx = fmaxf(mx, __shfl_xor_sync(0xffffffffu, mx, 1));
            mx = fmaxf(mx, __shfl_xor_sync(0xffffffffu, mx, 2));
            float sum = 0.f;
#pragma unroll
            for (int jj = 0; jj < 16; jj++) { sl[jj] = expf(sl[jj] - mx); sum += sl[jj]; }
            sum += __shfl_xor_sync(0xffffffffu, sum, 1);
            sum += __shfl_xor_sync(0xffffffffu, sum, 2);
            float inv = 1.0f / sum;
#pragma unroll
            for (int jj = 0; jj < 16; jj++) ps[row][j0 + jj] = sl[jj];
            __syncwarp();
            int d0 = l4 * 8;
            float acc[8];
#pragma unroll
            for (int dd = 0; dd < 8; dd++) acc[dd] = 0.f;
            for (int j = 0; j < 64; j++) {
                float p = ps[row][j];
#pragma unroll
                for (int dd = 0; dd < 8; dd++) acc[dd] += p * vs[j][d0 + dd];
            }
            float* o = g_att + (size_t)(wi * 64 + row) * C + hd * 32 + d0;
#pragma unroll
            for (int dd = 0; dd < 8; dd++) o[dd] = acc[dd] * inv;
        }
        gsync();

        // ---- proj GEMM (M=256, N=384, K=384, S=4) ----
        if (bid < 96) {
            int s = bid & 3, tile = bid >> 2;
            int mt = tile & 3, ntl = tile >> 2;
            gemm_core<0>(g_att, 384, P.proj_w + (size_t)blk * C * C, 384, 0,
                         g_part + (size_t)s * (L * C), C, mt * 64, ntl * 64, s * 96, 3, sm);
        }
        gsync();

        // ---- LN2 (+fold proj partials w/ unshift + bias + residual) -> z ----
        {
            const float* pb = P.proj_b + blk * C;
            const float* w  = P.ln2_w + blk * C;
            const float* bv = P.ln2_b + blk * C;
            for (int r = bid; r < 256; r += NCTA) {
                int h = r >> 4, wd = r & 15;
                int hs = (h + 12) & 15, ws_ = (wd + 12) & 15;
                int wi = ((hs >> 3) << 1) + (ws_ >> 3);
                int pos = ((hs & 7) << 3) + (ws_ & 7);
                int mw = wi * 64 + pos;
                float x0 = 0.f, x1 = 0.f, x2 = 0.f;
                if (tid < 128) {
                    float* tr = g_t + r * C;
                    float a0 = pb[tid], a1 = pb[tid + 128], a2 = pb[tid + 256];
#pragma unroll
                    for (int s = 0; s < 4; s++) {
                        const float* pq = g_part + (size_t)s * (L * C) + mw * C;
                        a0 += pq[tid]; a1 += pq[tid + 128]; a2 += pq[tid + 256];
                    }
                    x0 = tr[tid] + a0; x1 = tr[tid + 128] + a1; x2 = tr[tid + 256] + a2;
                    tr[tid] = x0; tr[tid + 128] = x1; tr[tid + 256] = x2;
                }
                float s = x0 + x1 + x2;
#pragma unroll
                for (int o = 16; o; o >>= 1) s += __shfl_xor_sync(0xffffffffu, s, o);
                if (tid < 128 && (tid & 31) == 0) red[tid >> 5] = s;
                __syncthreads();
                float mean = (red[0] + red[1] + red[2] + red[3]) * (1.f / 384.f);
                float d0 = x0 - mean, d1 = x1 - mean, d2 = x2 - mean;
                float s2 = d0 * d0 + d1 * d1 + d2 * d2;
#pragma unroll
                for (int o = 16; o; o >>= 1) s2 += __shfl_xor_sync(0xffffffffu, s2, o);
                __syncthreads();
                if (tid < 128 && (tid & 31) == 0) red[tid >> 5] = s2;
                __syncthreads();
                float var = (red[0] + red[1] + red[2] + red[3]) * (1.f / 384.f);
                float rstd = rsqrtf(var + 1e-5f);
                if (tid < 128) {
                    float* dst = g_z + r * C;
                    dst[tid]       = d0 * rstd * w[tid]       + bv[tid];
                    dst[tid + 128] = d1 * rstd * w[tid + 128] + bv[tid + 128];
                    dst[tid + 256] = d2 * rstd * w[tid + 256] + bv[tid + 256];
                }
                __syncthreads();
            }
        }
        gsync();

        // ---- fc1 GEMM (M=256, N=1536, K=384, S=1) + bias + gelu -> h1 ----
        if (bid < 96) {
            int mt = bid & 3, ntl = bid >> 2;
            gemm_core<1>(g_z, 384, P.fc1_w + (size_t)blk * MLPD * C, 384,
                         P.fc1_b + (size_t)blk * MLPD,
                         g_h1, MLPD, mt * 64, ntl * 64, 0, 12, sm);
        }
        gsync();

        // ---- fc2 GEMM (M=256, N=384, K=1536, S=6) ----
        if (bid < 144) {
            int s = bid % 6, tile = bid / 6;
            int mt = tile & 3, ntl = tile >> 2;
            gemm_core<0>(g_h1, MLPD, P.fc2_w + (size_t)blk * C * MLPD, MLPD, 0,
                         g_part + (size_t)s * (L * C), C, mt * 64, ntl * 64, s * 256, 8, sm);
        }
        gsync();
    }

    // ---- fold last fc2 into t ----
    {
        const float* fb = P.fc2_b + 11 * C;
        for (int i = bid * 256 + tid; i < L * C; i += NCTA * 256) {
            int n = i % C;
            float v = fb[n];
#pragma unroll
            for (int s = 0; s < 6; s++) v += g_part[(size_t)s * (L * C) + i];
            g_t[i] += v;
        }
    }
    gsync();

    // ---- decoder: skip 1x1 conv + d1 deconv+BN+ReLU ----
    if (bid < 96) {
        int o = bid % 3, pg = bid / 3;
        float (*ts)[384] = (float(*)[384])sm;
        for (int i = tid; i < 8 * 384; i += 256)
            ts[i / 384][i % 384] = g_t[(pg * 8 + i / 384) * C + (i % 384)];
        __syncthreads();
        float acc[8];
#pragma unroll
        for (int g = 0; g < 8; g++) acc[g] = P.dt1_b[o];
        for (int cc = 0; cc < C; cc++) {
            float wv = P.dt1_w[cc * 768 + o * 256 + tid];
#pragma unroll
            for (int g = 0; g < 8; g++) acc[g] += ts[g][cc] * wv;
        }
        float a = P.bn1_w[o] * INV_S, bbv = P.bn1_b[o];
        int k = tid >> 4, l = tid & 15;
#pragma unroll
        for (int g = 0; g < 8; g++) {
            int patch = pg * 8 + g;
            int h = patch >> 4, w = patch & 15;
            g_d1[o * 65536 + (h * 16 + k) * 256 + (w * 16 + l)] =
                fmaxf(0.f, acc[g] * a + bbv);
        }
    } else if (bid < 100) {
        int o = bid - 96;
        float acc = P.skip_b[o];
        for (int cc = 0; cc < C; cc++) acc += g_t[tid * C + cc] * P.skip_w[o * C + cc];
        g_skip[o * 256 + tid] = acc;
    }
}

// ---------------- decoder final (separate, fully parallel) ----------------
__global__ void final_kernel(const float* __restrict__ w2,
                             const float* __restrict__ b2, const float* __restrict__ bnw,
                             const float* __restrict__ bnb, float4* __restrict__ out)
{
    int idx4 = blockIdx.x * 256 + threadIdx.x;
    int idx = idx4 << 2;
    int o = idx >> 24;
    int rem = idx & 0xFFFFFF;
    int Y = rem >> 12, X = rem & 4095;
    int H = Y >> 4, k = Y & 15, W = X >> 4;
    float d0 = g_d1[0 * 65536 + H * 256 + W];
    float d1v = g_d1[1 * 65536 + H * 256 + W];
    float d2 = g_d1[2 * 65536 + H * 256 + W];
    float bnwo = bnw[o] * INV_S, bnbo = bnb[o], b2o = b2[o];
    int y0 = Y / 273;
    float fy = (float)(Y - y0 * 273) * (1.0f / 273.0f);
    int y1 = min(y0 + 1, 15);
    const float* sk = g_skip + o * 256;
    float r[4];
#pragma unroll
    for (int j = 0; j < 4; j++) {
        int Xj = X + j;
        int l = Xj & 15;
        int kl = k * 16 + l;
        float acc = b2o + d0 * w2[0 * 1024 + o * 256 + kl]
                        + d1v * w2[1 * 1024 + o * 256 + kl]
                        + d2 * w2[2 * 1024 + o * 256 + kl];
        acc = acc * bnwo + bnbo;
        int x0 = Xj / 273;
        float fx = (float)(Xj - x0 * 273) * (1.0f / 273.0f);
        int x1 = min(x0 + 1, 15);
        float v00 = sk[y0 * 16 + x0], v01 = sk[y0 * 16 + x1];
        float v10 = sk[y1 * 16 + x0], v11 = sk[y1 * 16 + x1];
        float vt = v00 + (v01 - v00) * fx;
        float vb = v10 + (v11 - v10) * fx;
        r[j] = acc + vt + (vb - vt) * fy;
    }
    out[idx4] = make_float4(r[0], r[1], r[2], r[3]);
}

// ---------------- host launch ----------------
extern "C" void kernel_launch(void* const* d_in, const int* in_sizes, int n_in,
                              void* d_out, int out_size)
{
    MegaParams P;
    P.x       = (const float*)d_in[0];
    P.patch_w = (const float*)d_in[1];
    P.patch_b = (const float*)d_in[2];
    P.pos     = (const float*)d_in[3];
    P.ln1_w   = (const float*)d_in[4];
    P.ln1_b   = (const float*)d_in[5];
    P.qkv_w   = (const float*)d_in[6];
    P.proj_w  = (const float*)d_in[7];
    P.proj_b  = (const float*)d_in[8];
    P.rpb     = (const float*)d_in[9];
    P.ln2_w   = (const float*)d_in[10];
    P.ln2_b   = (const float*)d_in[11];
    P.fc1_w   = (const float*)d_in[12];
    P.fc1_b   = (const float*)d_in[13];
    P.fc2_w   = (const float*)d_in[14];
    P.fc2_b   = (const float*)d_in[15];
    P.skip_w  = (const float*)d_in[16];
    P.skip_b  = (const float*)d_in[17];
    P.dt1_w   = (const float*)d_in[18];
    P.dt1_b   = (const float*)d_in[19];
    P.bn1_w   = (const float*)d_in[20];
    P.bn1_b   = (const float*)d_in[21];
    const float* dt2_w = (const float*)d_in[22];
    const float* dt2_b = (const float*)d_in[23];
    const float* bn2_w = (const float*)d_in[24];
    const float* bn2_b = (const float*)d_in[25];

    cudaFuncSetAttribute(mega, cudaFuncAttributeMaxDynamicSharedMemorySize, MEGA_SMEM);

    reset_kernel<<<1, 1>>>();
    mega<<<NCTA, 256, MEGA_SMEM>>>(P);
    final_kernel<<<65536, 256>>>(dt2_w, dt2_b, bn2_w, bn2_b, (float4*)d_out);
}